// round 8
// baseline (speedup 1.0000x reference)
#include <cuda_runtime.h>
#include <cuda_bf16.h>
#include <cstdint>

// Problem constants: B=4, N=2048 (1536 img + 512 txt), C=1024, H=16, d=64
#define BB     4
#define NSEQ   2048
#define CDIM   1024
#define NH     16
#define DH     64
#define IMGTOK 1536
#define CHUNK  512
#define MTOT   (BB * NSEQ)          // 8192
// softmax runs in exp2 domain: fold log2(e) into the Q scale
#define SCALE_LOG2E 0.18033688011112042f   // (1/8) * log2(e)

// Attention dynamic smem: 2x K(16KB) + 2x V(16KB) + P(16KB) = 80KB
#define ATTN_SMEM_FLOATS 20480
#define ATTN_SMEM_BYTES  (ATTN_SMEM_FLOATS * 4)

// Scratch (static device memory; allocation-free, graph-safe)
__device__ float g_Q[BB * NH * NSEQ * DH];   // [B,H,N,d]
__device__ float g_K[BB * NH * NSEQ * DH];
__device__ float g_V[BB * NH * NSEQ * DH];
__device__ float g_O[BB * NSEQ * CDIM];      // [B,N,C] attention output

// ---------------------------------------------------------------------------
// Common helpers
// ---------------------------------------------------------------------------
__device__ __forceinline__ void split_tf32(float x, uint32_t& hi, uint32_t& lo) {
    uint32_t xi = __float_as_uint(x);
    uint32_t h  = xi & 0xFFFFE000u;          // tf32-exact truncation
    hi = h;
    lo = __float_as_uint(x - __uint_as_float(h));   // exact residual
}

__device__ __forceinline__ void mma8(float4& d, const uint32_t a[4], const uint32_t b[2]) {
    asm volatile(
        "mma.sync.aligned.m16n8k8.row.col.f32.tf32.tf32.f32 "
        "{%0,%1,%2,%3}, {%4,%5,%6,%7}, {%8,%9}, {%0,%1,%2,%3};\n"
        : "+f"(d.x), "+f"(d.y), "+f"(d.z), "+f"(d.w)
        : "r"(a[0]), "r"(a[1]), "r"(a[2]), "r"(a[3]), "r"(b[0]), "r"(b[1]));
}

// guaranteed MUFU.EX2 regardless of compiler fast-math flags
__device__ __forceinline__ float fast_exp2(float x) {
    float r;
    asm("ex2.approx.f32 %0, %1;" : "=f"(r) : "f"(x));
    return r;
}

__device__ __forceinline__ void cp_async16(uint32_t dst_smem, const void* src) {
    asm volatile("cp.async.cg.shared.global [%0], [%1], 16;\n"
                 :: "r"(dst_smem), "l"(src) : "memory");
}
__device__ __forceinline__ void cp_async_commit() {
    asm volatile("cp.async.commit_group;\n" ::: "memory");
}
__device__ __forceinline__ void cp_async_wait0() {
    asm volatile("cp.async.wait_group 0;\n" ::: "memory");
}

// ---------------------------------------------------------------------------
// TF32 tensor-core GEMM (3xTF32): C = A @ W + bias.
// headmode=1: blockIdx.z in {0,1,2} -> (A,W,b), scatter to g_Q/g_K/g_V.
// headmode=0: A==nullptr means read g_O; plain row-major out.
// BM=BN=128, BK=16, 256 thr = 8 warps, warp tile 32x64.
// ---------------------------------------------------------------------------
struct GemmArgs {
    const float* A[3];
    const float* W[3];
    const float* bias[3];
};

__device__ __forceinline__ int swz(int r) {
    return ((r >> 2) & 3) | ((r & 2) << 1);
}
__device__ __forceinline__ int kgi(int k3) { return ((k3 & 8) >> 1) | (k3 & 3); }
__device__ __forceinline__ int kw (int k3) { return (k3 >> 2) & 1; }

__global__ __launch_bounds__(256)
void tf32_gemm_kernel(GemmArgs ga, float* __restrict__ outparam, int headmode)
{
    __shared__ __align__(16) float As[2][128][16];
    __shared__ __align__(16) float Bs[2][128][16];

    const int z = blockIdx.z;
    const float* __restrict__ A    = ga.A[z] ? ga.A[z] : g_O;
    const float* __restrict__ W    = ga.W[z];
    const float* __restrict__ bias = ga.bias[z];
    float* __restrict__ dst;
    if (headmode) dst = (z == 0) ? g_Q : (z == 1) ? g_K : g_V;
    else          dst = outparam;

    const int tid  = threadIdx.x;
    const int bm   = blockIdx.y * 128;
    const int bn   = blockIdx.x * 128;
    const int lane = tid & 31;
    const int wid  = tid >> 5;
    const int wm   = wid >> 1;
    const int wn   = wid & 1;
    const int g    = lane >> 2;
    const int q    = lane & 3;

    const int ar  = tid >> 1;
    const int ac  = (tid & 1) * 8;
    const int bkr = tid >> 5;
    const int bc  = (tid & 31) * 4;

    const float* Aptr = A + (size_t)(bm + ar) * CDIM + ac;
    const float* Wptr = W + (size_t)bkr * CDIM + bn + bc;

    float4 acc[2][8];
#pragma unroll
    for (int mt = 0; mt < 2; mt++)
#pragma unroll
        for (int nt = 0; nt < 8; nt++) acc[mt][nt] = make_float4(0.f, 0.f, 0.f, 0.f);

    float4 aR0, aR1, bR0, bR1;
    aR0 = *(const float4*)(Aptr);
    aR1 = *(const float4*)(Aptr + 4);
    bR0 = *(const float4*)(Wptr);
    bR1 = *(const float4*)(Wptr + 8 * CDIM);

    auto storeA = [&](int buf, float4 v0, float4 v1) {
        float vals[8] = {v0.x, v0.y, v0.z, v0.w, v1.x, v1.y, v1.z, v1.w};
        const int sA = swz(ar);
#pragma unroll
        for (int j = 0; j < 8; j++) {
            int k3  = ac + j;
            int col = ((kgi(k3) ^ sA) << 1) | kw(k3);
            As[buf][ar][col] = vals[j];
        }
    };
    auto storeB = [&](int buf, float4 v0, float4 v1) {
        float lo4[4] = {v0.x, v0.y, v0.z, v0.w};
        float hi4[4] = {v1.x, v1.y, v1.z, v1.w};
        const int k3a = bkr, k3b = bkr + 8;
        const int ga2 = kgi(k3a), wa = kw(k3a);
        const int gb  = kgi(k3b), wb = kw(k3b);
#pragma unroll
        for (int j = 0; j < 4; j++) {
            int n  = bc + j;
            int sn = swz(n);
            Bs[buf][n][((ga2 ^ sn) << 1) | wa] = lo4[j];
            Bs[buf][n][((gb  ^ sn) << 1) | wb] = hi4[j];
        }
    };

    storeA(0, aR0, aR1);
    storeB(0, bR0, bR1);
    __syncthreads();

    const int NT = CDIM / 16;   // 64
    for (int kt = 0; kt < NT; kt++) {
        const int cur = kt & 1;
        if (kt < NT - 1) {
            aR0 = *(const float4*)(Aptr + (kt + 1) * 16);
            aR1 = *(const float4*)(Aptr + (kt + 1) * 16 + 4);
            bR0 = *(const float4*)(Wptr + (size_t)(kt + 1) * 16 * CDIM);
            bR1 = *(const float4*)(Wptr + (size_t)((kt + 1) * 16 + 8) * CDIM);
        }
#pragma unroll
        for (int ks = 0; ks < 2; ks++) {
            uint32_t ahi[2][4], alo[2][4];
#pragma unroll
            for (int mt = 0; mt < 2; mt++) {
                int r0 = wm * 32 + mt * 16 + g;
                int r1 = r0 + 8;
                float2 a02 = *(const float2*)&As[cur][r0][((ks * 4 + q) ^ swz(r0)) << 1];
                float2 a13 = *(const float2*)&As[cur][r1][((ks * 4 + q) ^ swz(r1)) << 1];
                split_tf32(a02.x, ahi[mt][0], alo[mt][0]);
                split_tf32(a13.x, ahi[mt][1], alo[mt][1]);
                split_tf32(a02.y, ahi[mt][2], alo[mt][2]);
                split_tf32(a13.y, ahi[mt][3], alo[mt][3]);
            }
#pragma unroll
            for (int nt = 0; nt < 8; nt++) {
                int n = wn * 64 + nt * 8 + g;
                float2 bv = *(const float2*)&Bs[cur][n][((ks * 4 + q) ^ swz(n)) << 1];
                uint32_t bhi[2], blo[2];
                split_tf32(bv.x, bhi[0], blo[0]);
                split_tf32(bv.y, bhi[1], blo[1]);
#pragma unroll
                for (int mt = 0; mt < 2; mt++) {
                    mma8(acc[mt][nt], ahi[mt], bhi);
                    mma8(acc[mt][nt], ahi[mt], blo);
                    mma8(acc[mt][nt], alo[mt], bhi);
                }
            }
        }
        if (kt < NT - 1) {
            storeA(cur ^ 1, aR0, aR1);
            storeB(cur ^ 1, bR0, bR1);
        }
        __syncthreads();
    }

    // Epilogue: bias + write (c-fragment: rows g/g+8, cols 2q/2q+1)
#pragma unroll
    for (int mt = 0; mt < 2; mt++) {
        const int r0 = bm + wm * 32 + mt * 16 + g;
        const int r1 = r0 + 8;
#pragma unroll
        for (int nt = 0; nt < 8; nt++) {
            const int c0 = bn + wn * 64 + nt * 8 + 2 * q;
            const float b0 = bias[c0], b1 = bias[c0 + 1];
            float2 lo = make_float2(acc[mt][nt].x + b0, acc[mt][nt].y + b1);
            float2 hi = make_float2(acc[mt][nt].z + b0, acc[mt][nt].w + b1);
            if (headmode) {
                const int h  = c0 >> 6;
                const int dd = c0 & 63;
                const int ba0 = r0 >> 11, t0 = r0 & (NSEQ - 1);
                const int ba1 = r1 >> 11, t1 = r1 & (NSEQ - 1);
                *(float2*)&dst[(size_t)(((ba0 * NH + h) * NSEQ) + t0) * DH + dd] = lo;
                *(float2*)&dst[(size_t)(((ba1 * NH + h) * NSEQ) + t1) * DH + dd] = hi;
            } else {
                *(float2*)&dst[(size_t)r0 * CDIM + c0] = lo;
                *(float2*)&dst[(size_t)r1 * CDIM + c0] = hi;
            }
        }
    }
}

// ---------------------------------------------------------------------------
// Tensor-core flash attention (3xTF32), exp2-domain FA2 softmax (MUFU.EX2),
// double-buffered K/V tiles via cp.async.
// Grid (32 qtiles of 64 rows, h=16, b=4), 128 thr = 4 warps, warp = 16 rows.
// qt reversed so heavy text tiles schedule first.
// Dynamic smem layout (floats): K0[0,4096) K1[4096,8192) V0[8192,12288)
// V1[12288,16384) P[16384,20480) (per-warp 1024-float slices).
// ---------------------------------------------------------------------------
__global__ __launch_bounds__(128)
void attn_mma_kernel(void)
{
    extern __shared__ __align__(16) float dsmem[];

    const int tid  = threadIdx.x;
    const int lane = tid & 31;
    const int wid  = tid >> 5;
    const int g    = lane >> 2;       // 0..7
    const int q    = lane & 3;        // 0..3
    const int qt   = (int)gridDim.x - 1 - (int)blockIdx.x;   // heavy-first
    const int h    = blockIdx.y;
    const int b    = blockIdx.z;
    const int qbase = qt * 64;
    const int bh    = (b * NH + h) * NSEQ;

    float* const Pw = dsmem + 16384 + wid * 1024;   // 16 x 64 per warp

    const int r0 = qbase + wid * 16 + g;   // this thread's two q-rows
    const int r1 = r0 + 8;

    int kstart, kend;
    if (qbase < IMGTOK) { kstart = qbase & ~(CHUNK - 1); kend = kstart + CHUNK; }
    else                { kstart = 0;                    kend = qbase + 64;     }
    const int ntiles = (kend - kstart) >> 6;

    // tile loader: K into dsmem[buf*4096], V into dsmem[8192+buf*4096]
    auto load_tiles = [&](int buf, int k0) {
        const float* Kg = g_K + (size_t)(bh + k0) * DH;
        const float* Vg = g_V + (size_t)(bh + k0) * DH;
        float* Kd = dsmem + buf * 4096;
        float* Vd = dsmem + 8192 + buf * 4096;
#pragma unroll
        for (int i = 0; i < 8; i++) {
            const int idx = tid + i * 128;       // 0..1023 float4 slots
            const int r   = idx >> 4;
            const int c4  = (idx & 15) << 2;
            uint32_t kdst = (uint32_t)__cvta_generic_to_shared(
                                Kd + r * 64 + (c4 ^ ((r & 7) << 3)));
            uint32_t vdst = (uint32_t)__cvta_generic_to_shared(
                                Vd + r * 64 + (c4 ^ ((r & 3) << 3)));
            cp_async16(kdst, Kg + r * 64 + c4);
            cp_async16(vdst, Vg + r * 64 + c4);
        }
    };

    // prologue: start tile 0, and load Q fragments while it flies
    load_tiles(0, kstart);
    cp_async_commit();

    uint32_t qhi[8][4], qlo[8][4];
#pragma unroll
    for (int ks = 0; ks < 8; ks++) {
        const int c0 = ks * 8 + q, c1 = c0 + 4;
        float v0 = g_Q[(size_t)(bh + r0) * DH + c0] * SCALE_LOG2E;
        float v1 = g_Q[(size_t)(bh + r1) * DH + c0] * SCALE_LOG2E;
        float v2 = g_Q[(size_t)(bh + r0) * DH + c1] * SCALE_LOG2E;
        float v3 = g_Q[(size_t)(bh + r1) * DH + c1] * SCALE_LOG2E;
        split_tf32(v0, qhi[ks][0], qlo[ks][0]);
        split_tf32(v1, qhi[ks][1], qlo[ks][1]);
        split_tf32(v2, qhi[ks][2], qlo[ks][2]);
        split_tf32(v3, qhi[ks][3], qlo[ks][3]);
    }

    float4 o[8];
#pragma unroll
    for (int dt = 0; dt < 8; dt++) o[dt] = make_float4(0.f, 0.f, 0.f, 0.f);
    float m0 = -1e30f, m1 = -1e30f, l0 = 0.f, l1 = 0.f;

    cp_async_wait0();
    __syncthreads();

    for (int t = 0; t < ntiles; t++) {
        const int cur = t & 1;
        const int k0  = kstart + t * 64;

        // kick off next tile into the other buffer (overlaps with compute)
        if (t + 1 < ntiles) {
            load_tiles(cur ^ 1, k0 + 64);
            cp_async_commit();
        }

        const float* Kc = dsmem + cur * 4096;
        const float* Vc = dsmem + 8192 + cur * 4096;

        // ---- S = Q @ K^T (3xTF32), log2 domain ----
        float4 s4[8];
#pragma unroll
        for (int nt = 0; nt < 8; nt++) s4[nt] = make_float4(0.f, 0.f, 0.f, 0.f);
#pragma unroll
        for (int ks = 0; ks < 8; ks++) {
#pragma unroll
            for (int nt = 0; nt < 8; nt++) {
                const int krow = nt * 8 + g;
                const int sw   = (g & 7) << 3;
                float bv0 = Kc[krow * 64 + ((ks * 8 + q)     ^ sw)];
                float bv1 = Kc[krow * 64 + ((ks * 8 + q + 4) ^ sw)];
                uint32_t bhi[2], blo[2];
                split_tf32(bv0, bhi[0], blo[0]);
                split_tf32(bv1, bhi[1], blo[1]);
                mma8(s4[nt], qhi[ks], bhi);
                mma8(s4[nt], qhi[ks], blo);
                mma8(s4[nt], qlo[ks], bhi);
            }
        }

        // causal mask (only diagonal text tile)
        if (qbase >= IMGTOK && k0 == qbase) {
#pragma unroll
            for (int nt = 0; nt < 8; nt++) {
                const int kc0 = k0 + nt * 8 + 2 * q;
                const int kc1 = kc0 + 1;
                if (kc0 > r0) s4[nt].x = -1e30f;
                if (kc1 > r0) s4[nt].y = -1e30f;
                if (kc0 > r1) s4[nt].z = -1e30f;
                if (kc1 > r1) s4[nt].w = -1e30f;
            }
        }

        // ---- online softmax (row reduce over quad lanes 1,2) ----
        float tm0 = -1e30f, tm1 = -1e30f;
#pragma unroll
        for (int nt = 0; nt < 8; nt++) {
            tm0 = fmaxf(tm0, fmaxf(s4[nt].x, s4[nt].y));
            tm1 = fmaxf(tm1, fmaxf(s4[nt].z, s4[nt].w));
        }
        tm0 = fmaxf(tm0, __shfl_xor_sync(0xffffffffu, tm0, 1));
        tm0 = fmaxf(tm0, __shfl_xor_sync(0xffffffffu, tm0, 2));
        tm1 = fmaxf(tm1, __shfl_xor_sync(0xffffffffu, tm1, 1));
        tm1 = fmaxf(tm1, __shfl_xor_sync(0xffffffffu, tm1, 2));

        const float mn0 = fmaxf(m0, tm0);
        const float mn1 = fmaxf(m1, tm1);
        const float cr0 = fast_exp2(m0 - mn0);
        const float cr1 = fast_exp2(m1 - mn1);

        float ls0 = 0.f, ls1 = 0.f;
#pragma unroll
        for (int nt = 0; nt < 8; nt++) {
            s4[nt].x = fast_exp2(s4[nt].x - mn0);
            s4[nt].y = fast_exp2(s4[nt].y - mn0);
            s4[nt].z = fast_exp2(s4[nt].z - mn1);
            s4[nt].w = fast_exp2(s4[nt].w - mn1);
            ls0 += s4[nt].x + s4[nt].y;
            ls1 += s4[nt].z + s4[nt].w;
        }
        ls0 += __shfl_xor_sync(0xffffffffu, ls0, 1);
        ls0 += __shfl_xor_sync(0xffffffffu, ls0, 2);
        ls1 += __shfl_xor_sync(0xffffffffu, ls1, 1);
        ls1 += __shfl_xor_sync(0xffffffffu, ls1, 2);
        l0 = l0 * cr0 + ls0;
        l1 = l1 * cr1 + ls1;
        m0 = mn0; m1 = mn1;

#pragma unroll
        for (int dt = 0; dt < 8; dt++) {
            o[dt].x *= cr0; o[dt].y *= cr0;
            o[dt].z *= cr1; o[dt].w *= cr1;
        }

        // stage P into per-warp smem (swizzled), then P@V (3xTF32)
        const int swp = (g & 7) << 3;
#pragma unroll
        for (int nt = 0; nt < 8; nt++) {
            const int c0 = nt * 8 + 2 * q;
            Pw[g * 64 + (c0 ^ swp)]             = s4[nt].x;
            Pw[g * 64 + ((c0 + 1) ^ swp)]       = s4[nt].y;
            Pw[(g + 8) * 64 + (c0 ^ swp)]       = s4[nt].z;
            Pw[(g + 8) * 64 + ((c0 + 1) ^ swp)] = s4[nt].w;
        }
        __syncwarp();

#pragma unroll
        for (int ks = 0; ks < 8; ks++) {
            float pa0 = Pw[g * 64 + ((ks * 8 + q) ^ swp)];
            float pa1 = Pw[(g + 8) * 64 + ((ks * 8 + q) ^ swp)];
            float pa2 = Pw[g * 64 + ((ks * 8 + q + 4) ^ swp)];
            float pa3 = Pw[(g + 8) * 64 + ((ks * 8 + q + 4) ^ swp)];
            uint32_t phi[4], plo[4];
            split_tf32(pa0, phi[0], plo[0]);
            split_tf32(pa1, phi[1], plo[1]);
            split_tf32(pa2, phi[2], plo[2]);
            split_tf32(pa3, phi[3], plo[3]);
            const int swv = (q & 3) << 3;
#pragma unroll
            for (int dt = 0; dt < 8; dt++) {
                float bv0 = Vc[(ks * 8 + q) * 64     + ((dt * 8 + g) ^ swv)];
                float bv1 = Vc[(ks * 8 + q + 4) * 64 + ((dt * 8 + g) ^ swv)];
                uint32_t bhi[2], blo[2];
                split_tf32(bv0, bhi[0], blo[0]);
                split_tf32(bv1, bhi[1], blo[1]);
                mma8(o[dt], phi, bhi);
                mma8(o[dt], phi, blo);
                mma8(o[dt], plo, bhi);
            }
        }
        __syncwarp();

        // next tile's cp.asyncs must be complete, and everyone done reading
        // cur before it becomes the write target next iteration
        cp_async_wait0();
        __syncthreads();
    }

    // finalize + write to g_O [B,N,C]
    const float inv0 = 1.f / l0;
    const float inv1 = 1.f / l1;
#pragma unroll
    for (int dt = 0; dt < 8; dt++) {
        const int c = h * DH + dt * 8 + 2 * q;
        float2 lo = make_float2(o[dt].x * inv0, o[dt].y * inv0);
        float2 hi = make_float2(o[dt].z * inv1, o[dt].w * inv1);
        *(float2*)&g_O[(size_t)(b * NSEQ + r0) * CDIM + c] = lo;
        *(float2*)&g_O[(size_t)(b * NSEQ + r1) * CDIM + c] = hi;
    }
}

// ---------------------------------------------------------------------------
extern "C" void kernel_launch(void* const* d_in, const int* in_sizes, int n_in,
                              void* d_out, int out_size)
{
    const float* q  = (const float*)d_in[0];
    const float* kv = (const float*)d_in[1];
    const float* Wq = (const float*)d_in[2];
    const float* bq = (const float*)d_in[3];
    const float* Wk = (const float*)d_in[4];
    const float* bk = (const float*)d_in[5];
    const float* Wv = (const float*)d_in[6];
    const float* bv = (const float*)d_in[7];
    const float* Wo = (const float*)d_in[8];
    const float* bo = (const float*)d_in[9];
    float* out = (float*)d_out;

    // opt in to 80KB dynamic smem for the attention kernel (idempotent,
    // not a stream op -> graph-capture safe)
    cudaFuncSetAttribute(attn_mma_kernel,
                         cudaFuncAttributeMaxDynamicSharedMemorySize,
                         ATTN_SMEM_BYTES);

    // Merged Q/K/V projection: one launch, grid.z selects projection.
    GemmArgs qkv;
    qkv.A[0] = q;  qkv.A[1] = kv; qkv.A[2] = kv;
    qkv.W[0] = Wq; qkv.W[1] = Wk; qkv.W[2] = Wv;
    qkv.bias[0] = bq; qkv.bias[1] = bk; qkv.bias[2] = bv;
    dim3 qkv_grid(CDIM / 128, MTOT / 128, 3);       // (8, 64, 3)
    tf32_gemm_kernel<<<qkv_grid, 256>>>(qkv, nullptr, 1);   // -> g_Q/g_K/g_V

    attn_mma_kernel<<<dim3(NSEQ / 64, NH, BB), 128, ATTN_SMEM_BYTES>>>(); // -> g_O

    // Output projection: A = g_O (signalled by nullptr)
    GemmArgs op;
    op.A[0] = nullptr; op.A[1] = nullptr; op.A[2] = nullptr;
    op.W[0] = Wo;      op.W[1] = Wo;      op.W[2] = Wo;
    op.bias[0] = bo;   op.bias[1] = bo;   op.bias[2] = bo;
    dim3 out_grid(CDIM / 128, MTOT / 128, 1);
    tf32_gemm_kernel<<<out_grid, 256>>>(op, out, 0);        // -> d_out
}

// round 12
// speedup vs baseline: 1.1384x; 1.1384x over previous
#include <cuda_runtime.h>
#include <cuda_bf16.h>
#include <cstdint>

// Problem constants: B=4, N=2048 (1536 img + 512 txt), C=1024, H=16, d=64
#define BB     4
#define NSEQ   2048
#define CDIM   1024
#define NH     16
#define DH     64
#define IMGTOK 1536
#define CHUNK  512
#define MTOT   (BB * NSEQ)          // 8192
// softmax runs in exp2 domain: fold log2(e) into the Q scale
#define SCALE_LOG2E 0.18033688011112042f   // (1/8) * log2(e)

// Attention dynamic smem: 2x K(16KB) + 2x V(16KB) + P(16KB) = 80KB
#define ATTN_SMEM_FLOATS 20480
#define ATTN_SMEM_BYTES  (ATTN_SMEM_FLOATS * 4)

// Scratch (static device memory; allocation-free, graph-safe)
__device__ float g_Q[BB * NH * NSEQ * DH];   // [B,H,N,d]
__device__ float g_K[BB * NH * NSEQ * DH];
__device__ float g_V[BB * NH * NSEQ * DH];
__device__ float g_O[BB * NSEQ * CDIM];      // [B,N,C] attention output

// ---------------------------------------------------------------------------
// Common helpers
// ---------------------------------------------------------------------------
__device__ __forceinline__ void split_tf32(float x, uint32_t& hi, uint32_t& lo) {
    uint32_t xi = __float_as_uint(x);
    uint32_t h  = xi & 0xFFFFE000u;          // tf32-exact truncation
    hi = h;
    lo = __float_as_uint(x - __uint_as_float(h));   // exact residual
}

__device__ __forceinline__ void mma8(float4& d, const uint32_t a[4], const uint32_t b[2]) {
    asm volatile(
        "mma.sync.aligned.m16n8k8.row.col.f32.tf32.tf32.f32 "
        "{%0,%1,%2,%3}, {%4,%5,%6,%7}, {%8,%9}, {%0,%1,%2,%3};\n"
        : "+f"(d.x), "+f"(d.y), "+f"(d.z), "+f"(d.w)
        : "r"(a[0]), "r"(a[1]), "r"(a[2]), "r"(a[3]), "r"(b[0]), "r"(b[1]));
}

// guaranteed MUFU.EX2 regardless of compiler fast-math flags
__device__ __forceinline__ float fast_exp2(float x) {
    float r;
    asm("ex2.approx.f32 %0, %1;" : "=f"(r) : "f"(x));
    return r;
}

__device__ __forceinline__ void cp_async16(uint32_t dst_smem, const void* src) {
    asm volatile("cp.async.cg.shared.global [%0], [%1], 16;\n"
                 :: "r"(dst_smem), "l"(src) : "memory");
}
__device__ __forceinline__ void cp_async_commit() {
    asm volatile("cp.async.commit_group;\n" ::: "memory");
}
__device__ __forceinline__ void cp_async_wait0() {
    asm volatile("cp.async.wait_group 0;\n" ::: "memory");
}

// ---------------------------------------------------------------------------
// TF32 tensor-core GEMM (3xTF32): C = A @ W + bias.
// headmode=1: blockIdx.z in {0,1,2} -> (A,W,b), scatter to g_Q/g_K/g_V.
// headmode=0: A==nullptr means read g_O; plain row-major out.
// BM=64, BN=128, BK=16, 256 thr = 8 warps (2m x 4n), warp tile 32x32.
// Small BM keeps acc at 32 regs/thread -> 2 CTAs/SM (occupancy fix from
// R8 ncu: 155 regs forced 1 CTA/SM, tensor pipe stalled at 43%).
// ---------------------------------------------------------------------------
struct GemmArgs {
    const float* A[3];
    const float* W[3];
    const float* bias[3];
};

__device__ __forceinline__ int swz(int r) {
    return ((r >> 2) & 3) | ((r & 2) << 1);
}
__device__ __forceinline__ int kgi(int k3) { return ((k3 & 8) >> 1) | (k3 & 3); }
__device__ __forceinline__ int kw (int k3) { return (k3 >> 2) & 1; }

__global__ __launch_bounds__(256, 2)
void tf32_gemm_kernel(GemmArgs ga, float* __restrict__ outparam, int headmode)
{
    __shared__ __align__(16) float As[2][64][16];    // 8KB
    __shared__ __align__(16) float Bs[2][128][16];   // 16KB

    const int z = blockIdx.z;
    const float* __restrict__ A    = ga.A[z] ? ga.A[z] : g_O;
    const float* __restrict__ W    = ga.W[z];
    const float* __restrict__ bias = ga.bias[z];
    float* __restrict__ dst;
    if (headmode) dst = (z == 0) ? g_Q : (z == 1) ? g_K : g_V;
    else          dst = outparam;

    const int tid  = threadIdx.x;
    const int bm   = blockIdx.y * 64;
    const int bn   = blockIdx.x * 128;
    const int lane = tid & 31;
    const int wid  = tid >> 5;
    const int wm   = wid >> 2;          // 0..1
    const int wn   = wid & 3;           // 0..3
    const int g    = lane >> 2;
    const int q    = lane & 3;

    // global load mapping: A 64x16 = 256 float4 (1/thread), B 16x128 (2/thread)
    const int ar  = tid >> 2;           // 0..63
    const int ac  = (tid & 3) * 4;      // 0,4,8,12
    const int bkr = tid >> 5;           // 0..7 (rows bkr, bkr+8)
    const int bc  = (tid & 31) * 4;     // 0..124

    const float* Aptr = A + (size_t)(bm + ar) * CDIM + ac;
    const float* Wptr = W + (size_t)bkr * CDIM + bn + bc;

    float4 acc[2][4];
#pragma unroll
    for (int mt = 0; mt < 2; mt++)
#pragma unroll
        for (int nt = 0; nt < 4; nt++) acc[mt][nt] = make_float4(0.f, 0.f, 0.f, 0.f);

    float4 aR, bR0, bR1;
    aR  = *(const float4*)(Aptr);
    bR0 = *(const float4*)(Wptr);
    bR1 = *(const float4*)(Wptr + 8 * CDIM);

    auto storeA = [&](int buf, float4 v) {
        float vals[4] = {v.x, v.y, v.z, v.w};
        const int sA = swz(ar);
#pragma unroll
        for (int j = 0; j < 4; j++) {
            int k3  = ac + j;
            int col = ((kgi(k3) ^ sA) << 1) | kw(k3);
            As[buf][ar][col] = vals[j];
        }
    };
    auto storeB = [&](int buf, float4 v0, float4 v1) {
        float lo4[4] = {v0.x, v0.y, v0.z, v0.w};
        float hi4[4] = {v1.x, v1.y, v1.z, v1.w};
        const int k3a = bkr, k3b = bkr + 8;
        const int ga2 = kgi(k3a), wa = kw(k3a);
        const int gb  = kgi(k3b), wb = kw(k3b);
#pragma unroll
        for (int j = 0; j < 4; j++) {
            int n  = bc + j;
            int sn = swz(n);
            Bs[buf][n][((ga2 ^ sn) << 1) | wa] = lo4[j];
            Bs[buf][n][((gb  ^ sn) << 1) | wb] = hi4[j];
        }
    };

    storeA(0, aR);
    storeB(0, bR0, bR1);
    __syncthreads();

    const int NT = CDIM / 16;   // 64
    for (int kt = 0; kt < NT; kt++) {
        const int cur = kt & 1;
        if (kt < NT - 1) {
            aR  = *(const float4*)(Aptr + (kt + 1) * 16);
            bR0 = *(const float4*)(Wptr + (size_t)(kt + 1) * 16 * CDIM);
            bR1 = *(const float4*)(Wptr + (size_t)((kt + 1) * 16 + 8) * CDIM);
        }
#pragma unroll
        for (int ks = 0; ks < 2; ks++) {
            uint32_t ahi[2][4], alo[2][4];
#pragma unroll
            for (int mt = 0; mt < 2; mt++) {
                int r0 = wm * 32 + mt * 16 + g;
                int r1 = r0 + 8;
                float2 a02 = *(const float2*)&As[cur][r0][((ks * 4 + q) ^ swz(r0)) << 1];
                float2 a13 = *(const float2*)&As[cur][r1][((ks * 4 + q) ^ swz(r1)) << 1];
                split_tf32(a02.x, ahi[mt][0], alo[mt][0]);
                split_tf32(a13.x, ahi[mt][1], alo[mt][1]);
                split_tf32(a02.y, ahi[mt][2], alo[mt][2]);
                split_tf32(a13.y, ahi[mt][3], alo[mt][3]);
            }
#pragma unroll
            for (int nt = 0; nt < 4; nt++) {
                int n = wn * 32 + nt * 8 + g;
                float2 bv = *(const float2*)&Bs[cur][n][((ks * 4 + q) ^ swz(n)) << 1];
                uint32_t bhi[2], blo[2];
                split_tf32(bv.x, bhi[0], blo[0]);
                split_tf32(bv.y, bhi[1], blo[1]);
#pragma unroll
                for (int mt = 0; mt < 2; mt++) {
                    mma8(acc[mt][nt], ahi[mt], bhi);
                    mma8(acc[mt][nt], ahi[mt], blo);
                    mma8(acc[mt][nt], alo[mt], bhi);
                }
            }
        }
        if (kt < NT - 1) {
            storeA(cur ^ 1, aR);
            storeB(cur ^ 1, bR0, bR1);
        }
        __syncthreads();
    }

    // Epilogue: bias + write (c-fragment: rows g/g+8, cols 2q/2q+1)
#pragma unroll
    for (int mt = 0; mt < 2; mt++) {
        const int r0 = bm + wm * 32 + mt * 16 + g;
        const int r1 = r0 + 8;
#pragma unroll
        for (int nt = 0; nt < 4; nt++) {
            const int c0 = bn + wn * 32 + nt * 8 + 2 * q;
            const float b0 = bias[c0], b1 = bias[c0 + 1];
            float2 lo = make_float2(acc[mt][nt].x + b0, acc[mt][nt].y + b1);
            float2 hi = make_float2(acc[mt][nt].z + b0, acc[mt][nt].w + b1);
            if (headmode) {
                const int h  = c0 >> 6;
                const int dd = c0 & 63;
                const int ba0 = r0 >> 11, t0 = r0 & (NSEQ - 1);
                const int ba1 = r1 >> 11, t1 = r1 & (NSEQ - 1);
                *(float2*)&dst[(size_t)(((ba0 * NH + h) * NSEQ) + t0) * DH + dd] = lo;
                *(float2*)&dst[(size_t)(((ba1 * NH + h) * NSEQ) + t1) * DH + dd] = hi;
            } else {
                *(float2*)&dst[(size_t)r0 * CDIM + c0] = lo;
                *(float2*)&dst[(size_t)r1 * CDIM + c0] = hi;
            }
        }
    }
}

// ---------------------------------------------------------------------------
// Tensor-core flash attention (3xTF32), exp2-domain FA2 softmax (MUFU.EX2),
// double-buffered K/V tiles via cp.async.  (unchanged from R8 passing run)
// Grid (32 qtiles of 64 rows, h=16, b=4), 128 thr = 4 warps, warp = 16 rows.
// ---------------------------------------------------------------------------
__global__ __launch_bounds__(128)
void attn_mma_kernel(void)
{
    extern __shared__ __align__(16) float dsmem[];

    const int tid  = threadIdx.x;
    const int lane = tid & 31;
    const int wid  = tid >> 5;
    const int g    = lane >> 2;       // 0..7
    const int q    = lane & 3;        // 0..3
    const int qt   = (int)gridDim.x - 1 - (int)blockIdx.x;   // heavy-first
    const int h    = blockIdx.y;
    const int b    = blockIdx.z;
    const int qbase = qt * 64;
    const int bh    = (b * NH + h) * NSEQ;

    float* const Pw = dsmem + 16384 + wid * 1024;   // 16 x 64 per warp

    const int r0 = qbase + wid * 16 + g;   // this thread's two q-rows
    const int r1 = r0 + 8;

    int kstart, kend;
    if (qbase < IMGTOK) { kstart = qbase & ~(CHUNK - 1); kend = kstart + CHUNK; }
    else                { kstart = 0;                    kend = qbase + 64;     }
    const int ntiles = (kend - kstart) >> 6;

    // tile loader: K into dsmem[buf*4096], V into dsmem[8192+buf*4096]
    auto load_tiles = [&](int buf, int k0) {
        const float* Kg = g_K + (size_t)(bh + k0) * DH;
        const float* Vg = g_V + (size_t)(bh + k0) * DH;
        float* Kd = dsmem + buf * 4096;
        float* Vd = dsmem + 8192 + buf * 4096;
#pragma unroll
        for (int i = 0; i < 8; i++) {
            const int idx = tid + i * 128;       // 0..1023 float4 slots
            const int r   = idx >> 4;
            const int c4  = (idx & 15) << 2;
            uint32_t kdst = (uint32_t)__cvta_generic_to_shared(
                                Kd + r * 64 + (c4 ^ ((r & 7) << 3)));
            uint32_t vdst = (uint32_t)__cvta_generic_to_shared(
                                Vd + r * 64 + (c4 ^ ((r & 3) << 3)));
            cp_async16(kdst, Kg + r * 64 + c4);
            cp_async16(vdst, Vg + r * 64 + c4);
        }
    };

    // prologue: start tile 0, and load Q fragments while it flies
    load_tiles(0, kstart);
    cp_async_commit();

    uint32_t qhi[8][4], qlo[8][4];
#pragma unroll
    for (int ks = 0; ks < 8; ks++) {
        const int c0 = ks * 8 + q, c1 = c0 + 4;
        float v0 = g_Q[(size_t)(bh + r0) * DH + c0] * SCALE_LOG2E;
        float v1 = g_Q[(size_t)(bh + r1) * DH + c0] * SCALE_LOG2E;
        float v2 = g_Q[(size_t)(bh + r0) * DH + c1] * SCALE_LOG2E;
        float v3 = g_Q[(size_t)(bh + r1) * DH + c1] * SCALE_LOG2E;
        split_tf32(v0, qhi[ks][0], qlo[ks][0]);
        split_tf32(v1, qhi[ks][1], qlo[ks][1]);
        split_tf32(v2, qhi[ks][2], qlo[ks][2]);
        split_tf32(v3, qhi[ks][3], qlo[ks][3]);
    }

    float4 o[8];
#pragma unroll
    for (int dt = 0; dt < 8; dt++) o[dt] = make_float4(0.f, 0.f, 0.f, 0.f);
    float m0 = -1e30f, m1 = -1e30f, l0 = 0.f, l1 = 0.f;

    cp_async_wait0();
    __syncthreads();

    for (int t = 0; t < ntiles; t++) {
        const int cur = t & 1;
        const int k0  = kstart + t * 64;

        // kick off next tile into the other buffer (overlaps with compute)
        if (t + 1 < ntiles) {
            load_tiles(cur ^ 1, k0 + 64);
            cp_async_commit();
        }

        const float* Kc = dsmem + cur * 4096;
        const float* Vc = dsmem + 8192 + cur * 4096;

        // ---- S = Q @ K^T (3xTF32), log2 domain ----
        float4 s4[8];
#pragma unroll
        for (int nt = 0; nt < 8; nt++) s4[nt] = make_float4(0.f, 0.f, 0.f, 0.f);
#pragma unroll
        for (int ks = 0; ks < 8; ks++) {
#pragma unroll
            for (int nt = 0; nt < 8; nt++) {
                const int krow = nt * 8 + g;
                const int sw   = (g & 7) << 3;
                float bv0 = Kc[krow * 64 + ((ks * 8 + q)     ^ sw)];
                float bv1 = Kc[krow * 64 + ((ks * 8 + q + 4) ^ sw)];
                uint32_t bhi[2], blo[2];
                split_tf32(bv0, bhi[0], blo[0]);
                split_tf32(bv1, bhi[1], blo[1]);
                mma8(s4[nt], qhi[ks], bhi);
                mma8(s4[nt], qhi[ks], blo);
                mma8(s4[nt], qlo[ks], bhi);
            }
        }

        // causal mask (only diagonal text tile)
        if (qbase >= IMGTOK && k0 == qbase) {
#pragma unroll
            for (int nt = 0; nt < 8; nt++) {
                const int kc0 = k0 + nt * 8 + 2 * q;
                const int kc1 = kc0 + 1;
                if (kc0 > r0) s4[nt].x = -1e30f;
                if (kc1 > r0) s4[nt].y = -1e30f;
                if (kc0 > r1) s4[nt].z = -1e30f;
                if (kc1 > r1) s4[nt].w = -1e30f;
            }
        }

        // ---- online softmax (row reduce over quad lanes 1,2) ----
        float tm0 = -1e30f, tm1 = -1e30f;
#pragma unroll
        for (int nt = 0; nt < 8; nt++) {
            tm0 = fmaxf(tm0, fmaxf(s4[nt].x, s4[nt].y));
            tm1 = fmaxf(tm1, fmaxf(s4[nt].z, s4[nt].w));
        }
        tm0 = fmaxf(tm0, __shfl_xor_sync(0xffffffffu, tm0, 1));
        tm0 = fmaxf(tm0, __shfl_xor_sync(0xffffffffu, tm0, 2));
        tm1 = fmaxf(tm1, __shfl_xor_sync(0xffffffffu, tm1, 1));
        tm1 = fmaxf(tm1, __shfl_xor_sync(0xffffffffu, tm1, 2));

        const float mn0 = fmaxf(m0, tm0);
        const float mn1 = fmaxf(m1, tm1);
        const float cr0 = fast_exp2(m0 - mn0);
        const float cr1 = fast_exp2(m1 - mn1);

        float ls0 = 0.f, ls1 = 0.f;
#pragma unroll
        for (int nt = 0; nt < 8; nt++) {
            s4[nt].x = fast_exp2(s4[nt].x - mn0);
            s4[nt].y = fast_exp2(s4[nt].y - mn0);
            s4[nt].z = fast_exp2(s4[nt].z - mn1);
            s4[nt].w = fast_exp2(s4[nt].w - mn1);
            ls0 += s4[nt].x + s4[nt].y;
            ls1 += s4[nt].z + s4[nt].w;
        }
        ls0 += __shfl_xor_sync(0xffffffffu, ls0, 1);
        ls0 += __shfl_xor_sync(0xffffffffu, ls0, 2);
        ls1 += __shfl_xor_sync(0xffffffffu, ls1, 1);
        ls1 += __shfl_xor_sync(0xffffffffu, ls1, 2);
        l0 = l0 * cr0 + ls0;
        l1 = l1 * cr1 + ls1;
        m0 = mn0; m1 = mn1;

#pragma unroll
        for (int dt = 0; dt < 8; dt++) {
            o[dt].x *= cr0; o[dt].y *= cr0;
            o[dt].z *= cr1; o[dt].w *= cr1;
        }

        // stage P into per-warp smem (swizzled), then P@V (3xTF32)
        const int swp = (g & 7) << 3;
#pragma unroll
        for (int nt = 0; nt < 8; nt++) {
            const int c0 = nt * 8 + 2 * q;
            Pw[g * 64 + (c0 ^ swp)]             = s4[nt].x;
            Pw[g * 64 + ((c0 + 1) ^ swp)]       = s4[nt].y;
            Pw[(g + 8) * 64 + (c0 ^ swp)]       = s4[nt].z;
            Pw[(g + 8) * 64 + ((c0 + 1) ^ swp)] = s4[nt].w;
        }
        __syncwarp();

#pragma unroll
        for (int ks = 0; ks < 8; ks++) {
            float pa0 = Pw[g * 64 + ((ks * 8 + q) ^ swp)];
            float pa1 = Pw[(g + 8) * 64 + ((ks * 8 + q) ^ swp)];
            float pa2 = Pw[g * 64 + ((ks * 8 + q + 4) ^ swp)];
            float pa3 = Pw[(g + 8) * 64 + ((ks * 8 + q + 4) ^ swp)];
            uint32_t phi[4], plo[4];
            split_tf32(pa0, phi[0], plo[0]);
            split_tf32(pa1, phi[1], plo[1]);
            split_tf32(pa2, phi[2], plo[2]);
            split_tf32(pa3, phi[3], plo[3]);
            const int swv = (q & 3) << 3;
#pragma unroll
            for (int dt = 0; dt < 8; dt++) {
                float bv0 = Vc[(ks * 8 + q) * 64     + ((dt * 8 + g) ^ swv)];
                float bv1 = Vc[(ks * 8 + q + 4) * 64 + ((dt * 8 + g) ^ swv)];
                uint32_t bhi[2], blo[2];
                split_tf32(bv0, bhi[0], blo[0]);
                split_tf32(bv1, bhi[1], blo[1]);
                mma8(o[dt], phi, bhi);
                mma8(o[dt], phi, blo);
                mma8(o[dt], plo, bhi);
            }
        }
        __syncwarp();

        // next tile's cp.asyncs must be complete, and everyone done reading
        // cur before it becomes the write target next iteration
        cp_async_wait0();
        __syncthreads();
    }

    // finalize + write to g_O [B,N,C]
    const float inv0 = 1.f / l0;
    const float inv1 = 1.f / l1;
#pragma unroll
    for (int dt = 0; dt < 8; dt++) {
        const int c = h * DH + dt * 8 + 2 * q;
        float2 lo = make_float2(o[dt].x * inv0, o[dt].y * inv0);
        float2 hi = make_float2(o[dt].z * inv1, o[dt].w * inv1);
        *(float2*)&g_O[(size_t)(b * NSEQ + r0) * CDIM + c] = lo;
        *(float2*)&g_O[(size_t)(b * NSEQ + r1) * CDIM + c] = hi;
    }
}

// ---------------------------------------------------------------------------
extern "C" void kernel_launch(void* const* d_in, const int* in_sizes, int n_in,
                              void* d_out, int out_size)
{
    const float* q  = (const float*)d_in[0];
    const float* kv = (const float*)d_in[1];
    const float* Wq = (const float*)d_in[2];
    const float* bq = (const float*)d_in[3];
    const float* Wk = (const float*)d_in[4];
    const float* bk = (const float*)d_in[5];
    const float* Wv = (const float*)d_in[6];
    const float* bv = (const float*)d_in[7];
    const float* Wo = (const float*)d_in[8];
    const float* bo = (const float*)d_in[9];
    float* out = (float*)d_out;

    // opt in to 80KB dynamic smem for the attention kernel (idempotent,
    // not a stream op -> graph-capture safe)
    cudaFuncSetAttribute(attn_mma_kernel,
                         cudaFuncAttributeMaxDynamicSharedMemorySize,
                         ATTN_SMEM_BYTES);

    // Merged Q/K/V projection: one launch, grid.z selects projection.
    GemmArgs qkv;
    qkv.A[0] = q;  qkv.A[1] = kv; qkv.A[2] = kv;
    qkv.W[0] = Wq; qkv.W[1] = Wk; qkv.W[2] = Wv;
    qkv.bias[0] = bq; qkv.bias[1] = bk; qkv.bias[2] = bv;
    dim3 qkv_grid(CDIM / 128, MTOT / 64, 3);        // (8, 128, 3)
    tf32_gemm_kernel<<<qkv_grid, 256>>>(qkv, nullptr, 1);   // -> g_Q/g_K/g_V

    attn_mma_kernel<<<dim3(NSEQ / 64, NH, BB), 128, ATTN_SMEM_BYTES>>>(); // -> g_O

    // Output projection: A = g_O (signalled by nullptr)
    GemmArgs op;
    op.A[0] = nullptr; op.A[1] = nullptr; op.A[2] = nullptr;
    op.W[0] = Wo;      op.W[1] = Wo;      op.W[2] = Wo;
    op.bias[0] = bo;   op.bias[1] = bo;   op.bias[2] = bo;
    dim3 out_grid(CDIM / 128, MTOT / 64, 1);        // (8, 128)
    tf32_gemm_kernel<<<out_grid, 256>>>(op, out, 0);        // -> d_out
}